// round 6
// baseline (speedup 1.0000x reference)
#include <cuda_runtime.h>
#include <cstdint>

#define B_    8
#define S_    4096
#define H_    16
#define NTILES 2048      // (B*H*S)/256
#define TPB   256        // 8 warps, each warp owns 32 rows (two m16 blocks) of the 256-row tile
#define NWARP 8
#define GRID  148
#define EPSf  1e-5f

typedef uint32_t u32;
typedef uint64_t u64;

// ---------------- SMEM layout (bytes) ----------------
// B-fragments per mma position, per lane: uint4 {b0h, b1h, b0l, b1l}
#define OFF_WK   0            // 32 positions * 32 lanes * 16B = 16384
#define OFF_WV   16384
#define OFF_WQ   32768
#define OFF_W1   49152        // 64 positions = 32768
#define OFF_W2   81920        // 64 positions = 32768
#define OFF_PRM  114688       // fg[64], l1w[64], l1b[64], b2[64], l2w[128], l2b[128] floats
#define SMEM_TOTAL (114688 + 512 * 4)

// split (e,o) fp32 pair into bf16x2 hi (lo half = e) and bf16x2 residual lo
__device__ __forceinline__ void split2(float e, float o, u32 &hi, u32 &lo) {
    u32 h; asm("cvt.rn.bf16x2.f32 %0, %1, %2;" : "=r"(h) : "f"(o), "f"(e));
    float he = __uint_as_float(h << 16);
    float ho = __uint_as_float(h & 0xffff0000u);
    float re = e - he, ro = o - ho;
    asm("cvt.rn.bf16x2.f32 %0, %1, %2;" : "=r"(lo) : "f"(ro), "f"(re));
    hi = h;
}

__device__ __forceinline__ void mma16816(float *c,
                                         const u32 *a, u32 b0, u32 b1) {
    asm volatile("mma.sync.aligned.m16n8k16.row.col.f32.bf16.bf16.f32 "
                 "{%0,%1,%2,%3}, {%4,%5,%6,%7}, {%8,%9}, {%0,%1,%2,%3};"
                 : "+f"(c[0]), "+f"(c[1]), "+f"(c[2]), "+f"(c[3])
                 : "r"(a[0]), "r"(a[1]), "r"(a[2]), "r"(a[3]), "r"(b0), "r"(b1));
}

// Dual-row-block GEMM: one B-fragment read feeds 6 MMAs (3 passes x 2 blocks).
template<int NT, int KT>
__device__ __forceinline__ void do_gemm2(float (*c0)[4], float (*c1)[4],
                                         const u32 *ah0, const u32 *al0,
                                         const u32 *ah1, const u32 *al1,
                                         const uint4 *Bsm, int lane) {
#pragma unroll
    for (int kt = 0; kt < KT; kt++) {
#pragma unroll
        for (int nt = 0; nt < NT; nt++) {
            const int m = nt * KT + kt;
            uint4 p = Bsm[m * 32 + lane];   // {b0h, b1h, b0l, b1l}
            mma16816(c0[nt], ah0 + 4*kt, p.x, p.y);
            mma16816(c0[nt], ah0 + 4*kt, p.z, p.w);
            mma16816(c0[nt], al0 + 4*kt, p.x, p.y);
            mma16816(c1[nt], ah1 + 4*kt, p.x, p.y);
            mma16816(c1[nt], ah1 + 4*kt, p.z, p.w);
            mma16816(c1[nt], al1 + 4*kt, p.x, p.y);
        }
    }
}

// Stage weight matrix W [N][K] row-major fp32 -> per-lane B fragments (split) in smem.
__device__ __forceinline__ void stageB(uint4 *dst, const float * __restrict__ W,
                                       int NT, int KT, int K, int wid, int lane) {
    const int g = lane >> 2, t = lane & 3;
#pragma unroll 1
    for (int m = wid; m < NT * KT; m += NWARP) {
        int nt = m / KT, kt = m - nt * KT;
        const float *row = W + (nt * 8 + g) * K + kt * 16 + 2 * t;
        u32 h0, l0, h1, l1;
        split2(row[0], row[1], h0, l0);
        split2(row[8], row[9], h1, l1);
        uint4 v = { h0, h1, l0, l1 };
        dst[m * 32 + lane] = v;
    }
}

// Load one kt-step of A (16 fp32 across rows g,g+8) from two gmem row pointers, split.
__device__ __forceinline__ void loadA_kt(const float * __restrict__ r0,
                                         const float * __restrict__ r1,
                                         int t, u32 *ah, u32 *al) {
    float2 e0 = *(const float2 *)(r0 + 2 * t);
    float2 e1 = *(const float2 *)(r1 + 2 * t);
    float2 e2 = *(const float2 *)(r0 + 2 * t + 8);
    float2 e3 = *(const float2 *)(r1 + 2 * t + 8);
    split2(e0.x, e0.y, ah[0], al[0]);
    split2(e1.x, e1.y, ah[1], al[1]);
    split2(e2.x, e2.y, ah[2], al[2]);
    split2(e3.x, e3.y, ah[3], al[3]);
}

__device__ __forceinline__ float qreduce(float v) {
    v += __shfl_xor_sync(0xffffffffu, v, 1);
    v += __shfl_xor_sync(0xffffffffu, v, 2);
    return v;
}

__device__ __forceinline__ int qoff_of(int row) {
    int s = row & (S_ - 1);
    int h = (row >> 12) & (H_ - 1);
    int b = row >> 16;
    return (((b << 12) | s) << 10) + (h << 6);
}

extern __shared__ char smem[];

__global__ void __launch_bounds__(TPB, 1) mhba_hmma_kernel(
    const float* __restrict__ Qin, const float* __restrict__ Kin,
    const float* __restrict__ Vin, const float* __restrict__ MEM,
    const float* __restrict__ Wq,  const float* __restrict__ Wk,
    const float* __restrict__ Wv,  const float* __restrict__ FG,
    const float* __restrict__ LN1W, const float* __restrict__ LN1B,
    const float* __restrict__ W1,
    const float* __restrict__ LN2W, const float* __restrict__ LN2B,
    const float* __restrict__ W2,  const float* __restrict__ B2,
    float* __restrict__ OUT, float* __restrict__ CM)
{
    const int tid  = threadIdx.x;
    const int wid  = tid >> 5;
    const int lane = tid & 31;
    const int g = lane >> 2, t = lane & 3;

    float *pf = (float *)(smem + OFF_PRM);
    if (tid < 64) {
        pf[tid]       = FG[tid];
        pf[64 + tid]  = LN1W[tid];
        pf[128 + tid] = LN1B[tid];
        pf[192 + tid] = B2[tid];
    }
    if (tid < 128) {
        pf[256 + tid] = LN2W[tid];
        pf[384 + tid] = LN2B[tid];
    }
    stageB((uint4 *)(smem + OFF_WK), Wk, 8,  4, 64,  wid, lane);
    stageB((uint4 *)(smem + OFF_WV), Wv, 8,  4, 64,  wid, lane);
    stageB((uint4 *)(smem + OFF_WQ), Wq, 8,  4, 64,  wid, lane);
    stageB((uint4 *)(smem + OFF_W1), W1, 16, 4, 64,  wid, lane);
    stageB((uint4 *)(smem + OFF_W2), W2, 8,  8, 128, wid, lane);
    __syncthreads();

    const uint4 *BWk = (const uint4 *)(smem + OFF_WK);
    const uint4 *BWv = (const uint4 *)(smem + OFF_WV);
    const uint4 *BWq = (const uint4 *)(smem + OFF_WQ);
    const uint4 *BW1 = (const uint4 *)(smem + OFF_W1);
    const uint4 *BW2 = (const uint4 *)(smem + OFF_W2);

#pragma unroll 1
    for (int tile = blockIdx.x; tile < NTILES; tile += gridDim.x) {
        const int rbase = tile * 256 + wid * 32;
        int qA[2], qB[2], mA[2], mB[2];
#pragma unroll
        for (int blk = 0; blk < 2; blk++) {
            int r0 = rbase + blk * 16 + g;
            int r1 = r0 + 8;
            qA[blk] = qoff_of(r0); qB[blk] = qoff_of(r1);
            mA[blk] = r0 << 6;     mB[blk] = r1 << 6;
        }

        u32 ah[2][16], al[2][16];

        // ---------- GEMM1: kp = Xk @ Wk^T ----------
#pragma unroll
        for (int blk = 0; blk < 2; blk++)
#pragma unroll
            for (int kt = 0; kt < 4; kt++)
                loadA_kt(Kin + qA[blk] + kt * 16, Kin + qB[blk] + kt * 16, t,
                         ah[blk] + 4 * kt, al[blk] + 4 * kt);
        float ckp[2][8][4];
#pragma unroll
        for (int blk = 0; blk < 2; blk++)
#pragma unroll
            for (int i = 0; i < 8; i++)
                { ckp[blk][i][0]=0.f; ckp[blk][i][1]=0.f; ckp[blk][i][2]=0.f; ckp[blk][i][3]=0.f; }
        do_gemm2<8, 4>(ckp[0], ckp[1], ah[0], al[0], ah[1], al[1], BWk, lane);

        // ---------- GEMM2: vp = Xv @ Wv^T ----------
#pragma unroll
        for (int blk = 0; blk < 2; blk++)
#pragma unroll
            for (int kt = 0; kt < 4; kt++)
                loadA_kt(Vin + qA[blk] + kt * 16, Vin + qB[blk] + kt * 16, t,
                         ah[blk] + 4 * kt, al[blk] + 4 * kt);
        float cvp[2][8][4];
#pragma unroll
        for (int blk = 0; blk < 2; blk++)
#pragma unroll
            for (int i = 0; i < 8; i++)
                { cvp[blk][i][0]=0.f; cvp[blk][i][1]=0.f; cvp[blk][i][2]=0.f; cvp[blk][i][3]=0.f; }
        do_gemm2<8, 4>(cvp[0], cvp[1], ah[0], al[0], ah[1], al[1], BWv, lane);

        // ---------- gate -> cur_mem (store), keep cm in cvp ----------
#pragma unroll
        for (int blk = 0; blk < 2; blk++) {
#pragma unroll
            for (int nt = 0; nt < 8; nt++) {
                const int colb = nt * 8 + 2 * t;
                float2 fg = *(const float2 *)(pf + colb);
                float2 m0 = *(const float2 *)(MEM + mA[blk] + colb);
                float2 m1 = *(const float2 *)(MEM + mB[blk] + colb);
                float fmx, cell;
                fmx  = fg.x * m0.x; cell = fmaf(ckp[blk][nt][0], cvp[blk][nt][0], fmx);
                float c0 = fmaf(1.f - fg.x, cell, fmx);
                fmx  = fg.y * m0.y; cell = fmaf(ckp[blk][nt][1], cvp[blk][nt][1], fmx);
                float c1 = fmaf(1.f - fg.y, cell, fmx);
                fmx  = fg.x * m1.x; cell = fmaf(ckp[blk][nt][2], cvp[blk][nt][2], fmx);
                float c2 = fmaf(1.f - fg.x, cell, fmx);
                fmx  = fg.y * m1.y; cell = fmaf(ckp[blk][nt][3], cvp[blk][nt][3], fmx);
                float c3 = fmaf(1.f - fg.y, cell, fmx);
                *(float2 *)(CM + mA[blk] + colb) = make_float2(c0, c1);
                *(float2 *)(CM + mB[blk] + colb) = make_float2(c2, c3);
                cvp[blk][nt][0] = c0; cvp[blk][nt][1] = c1;
                cvp[blk][nt][2] = c2; cvp[blk][nt][3] = c3;
            }
        }

        // ---------- GEMM3: qp = Xq @ Wq^T ----------
#pragma unroll
        for (int blk = 0; blk < 2; blk++)
#pragma unroll
            for (int kt = 0; kt < 4; kt++)
                loadA_kt(Qin + qA[blk] + kt * 16, Qin + qB[blk] + kt * 16, t,
                         ah[blk] + 4 * kt, al[blk] + 4 * kt);
#pragma unroll
        for (int blk = 0; blk < 2; blk++)
#pragma unroll
            for (int i = 0; i < 8; i++)
                { ckp[blk][i][0]=0.f; ckp[blk][i][1]=0.f; ckp[blk][i][2]=0.f; ckp[blk][i][3]=0.f; }
        do_gemm2<8, 4>(ckp[0], ckp[1], ah[0], al[0], ah[1], al[1], BWq, lane);

        // ---------- cv = qp * cm ; LN1 ; frags ----------
#pragma unroll
        for (int blk = 0; blk < 2; blk++) {
#pragma unroll
            for (int nt = 0; nt < 8; nt++) {
                cvp[blk][nt][0] *= ckp[blk][nt][0]; cvp[blk][nt][1] *= ckp[blk][nt][1];
                cvp[blk][nt][2] *= ckp[blk][nt][2]; cvp[blk][nt][3] *= ckp[blk][nt][3];
            }
            float s0 = 0.f, sq0 = 0.f, s1 = 0.f, sq1 = 0.f;
#pragma unroll
            for (int nt = 0; nt < 8; nt++) {
                s0 += cvp[blk][nt][0] + cvp[blk][nt][1];
                sq0 = fmaf(cvp[blk][nt][0], cvp[blk][nt][0], fmaf(cvp[blk][nt][1], cvp[blk][nt][1], sq0));
                s1 += cvp[blk][nt][2] + cvp[blk][nt][3];
                sq1 = fmaf(cvp[blk][nt][2], cvp[blk][nt][2], fmaf(cvp[blk][nt][3], cvp[blk][nt][3], sq1));
            }
            s0 = qreduce(s0); sq0 = qreduce(sq0);
            s1 = qreduce(s1); sq1 = qreduce(sq1);
            float mu0 = s0 * (1.f / 64.f);
            float rs0 = rsqrtf(sq0 * (1.f / 64.f) - mu0 * mu0 + EPSf);
            float mu1 = s1 * (1.f / 64.f);
            float rs1 = rsqrtf(sq1 * (1.f / 64.f) - mu1 * mu1 + EPSf);
#pragma unroll
            for (int nt = 0; nt < 8; nt++) {
                const int colb = nt * 8 + 2 * t;
                float2 w  = *(const float2 *)(pf + 64 + colb);
                float2 bb = *(const float2 *)(pf + 128 + colb);
                cvp[blk][nt][0] = fmaf((cvp[blk][nt][0] - mu0) * rs0, w.x, bb.x);
                cvp[blk][nt][1] = fmaf((cvp[blk][nt][1] - mu0) * rs0, w.y, bb.y);
                cvp[blk][nt][2] = fmaf((cvp[blk][nt][2] - mu1) * rs1, w.x, bb.x);
                cvp[blk][nt][3] = fmaf((cvp[blk][nt][3] - mu1) * rs1, w.y, bb.y);
            }
#pragma unroll
            for (int kt = 0; kt < 4; kt++) {
                split2(cvp[blk][2*kt][0],   cvp[blk][2*kt][1],   ah[blk][4*kt+0], al[blk][4*kt+0]);
                split2(cvp[blk][2*kt][2],   cvp[blk][2*kt][3],   ah[blk][4*kt+1], al[blk][4*kt+1]);
                split2(cvp[blk][2*kt+1][0], cvp[blk][2*kt+1][1], ah[blk][4*kt+2], al[blk][4*kt+2]);
                split2(cvp[blk][2*kt+1][2], cvp[blk][2*kt+1][3], ah[blk][4*kt+3], al[blk][4*kt+3]);
            }
        }

        // ---------- GEMM4: h1 = ln1cv @ W1^T  (N=128) ----------
        float h1[2][16][4];
#pragma unroll
        for (int blk = 0; blk < 2; blk++)
#pragma unroll
            for (int i = 0; i < 16; i++)
                { h1[blk][i][0]=0.f; h1[blk][i][1]=0.f; h1[blk][i][2]=0.f; h1[blk][i][3]=0.f; }
        do_gemm2<16, 4>(h1[0], h1[1], ah[0], al[0], ah[1], al[1], BW1, lane);

        // ---------- LN2 ; frags (K=128) ----------
        u32 ah2[2][32], al2[2][32];
#pragma unroll
        for (int blk = 0; blk < 2; blk++) {
            float s0 = 0.f, sq0 = 0.f, s1 = 0.f, sq1 = 0.f;
#pragma unroll
            for (int nt = 0; nt < 16; nt++) {
                s0 += h1[blk][nt][0] + h1[blk][nt][1];
                sq0 = fmaf(h1[blk][nt][0], h1[blk][nt][0], fmaf(h1[blk][nt][1], h1[blk][nt][1], sq0));
                s1 += h1[blk][nt][2] + h1[blk][nt][3];
                sq1 = fmaf(h1[blk][nt][2], h1[blk][nt][2], fmaf(h1[blk][nt][3], h1[blk][nt][3], sq1));
            }
            s0 = qreduce(s0); sq0 = qreduce(sq0);
            s1 = qreduce(s1); sq1 = qreduce(sq1);
            float mu0 = s0 * (1.f / 128.f);
            float rs0 = rsqrtf(sq0 * (1.f / 128.f) - mu0 * mu0 + EPSf);
            float mu1 = s1 * (1.f / 128.f);
            float rs1 = rsqrtf(sq1 * (1.f / 128.f) - mu1 * mu1 + EPSf);
#pragma unroll
            for (int nt = 0; nt < 16; nt++) {
                const int colb = nt * 8 + 2 * t;
                float2 w  = *(const float2 *)(pf + 256 + colb);
                float2 bb = *(const float2 *)(pf + 384 + colb);
                h1[blk][nt][0] = fmaf((h1[blk][nt][0] - mu0) * rs0, w.x, bb.x);
                h1[blk][nt][1] = fmaf((h1[blk][nt][1] - mu0) * rs0, w.y, bb.y);
                h1[blk][nt][2] = fmaf((h1[blk][nt][2] - mu1) * rs1, w.x, bb.x);
                h1[blk][nt][3] = fmaf((h1[blk][nt][3] - mu1) * rs1, w.y, bb.y);
            }
#pragma unroll
            for (int kt = 0; kt < 8; kt++) {
                split2(h1[blk][2*kt][0],   h1[blk][2*kt][1],   ah2[blk][4*kt+0], al2[blk][4*kt+0]);
                split2(h1[blk][2*kt][2],   h1[blk][2*kt][3],   ah2[blk][4*kt+1], al2[blk][4*kt+1]);
                split2(h1[blk][2*kt+1][0], h1[blk][2*kt+1][1], ah2[blk][4*kt+2], al2[blk][4*kt+2]);
                split2(h1[blk][2*kt+1][2], h1[blk][2*kt+1][3], ah2[blk][4*kt+3], al2[blk][4*kt+3]);
            }
        }

        // ---------- GEMM5: out = ln2h1 @ W2^T + b2 ----------
        float co[2][8][4];
#pragma unroll
        for (int blk = 0; blk < 2; blk++)
#pragma unroll
            for (int i = 0; i < 8; i++)
                { co[blk][i][0]=0.f; co[blk][i][1]=0.f; co[blk][i][2]=0.f; co[blk][i][3]=0.f; }
        do_gemm2<8, 8>(co[0], co[1], ah2[0], al2[0], ah2[1], al2[1], BW2, lane);

#pragma unroll
        for (int blk = 0; blk < 2; blk++)
#pragma unroll
            for (int nt = 0; nt < 8; nt++) {
                const int colb = nt * 8 + 2 * t;
                float2 b2v = *(const float2 *)(pf + 192 + colb);
                *(float2 *)(OUT + qA[blk] + colb) =
                    make_float2(co[blk][nt][0] + b2v.x, co[blk][nt][1] + b2v.y);
                *(float2 *)(OUT + qB[blk] + colb) =
                    make_float2(co[blk][nt][2] + b2v.x, co[blk][nt][3] + b2v.y);
            }
    }
}

extern "C" void kernel_launch(void* const* d_in, const int* in_sizes, int n_in,
                              void* d_out, int out_size) {
    const float* Qin  = (const float*)d_in[0];
    const float* Kin  = (const float*)d_in[1];
    const float* Vin  = (const float*)d_in[2];
    const float* MEM  = (const float*)d_in[3];
    const float* Wq   = (const float*)d_in[4];
    const float* Wk   = (const float*)d_in[5];
    const float* Wv   = (const float*)d_in[6];
    const float* FG   = (const float*)d_in[7];
    const float* LN1W = (const float*)d_in[8];
    const float* LN1B = (const float*)d_in[9];
    const float* W1   = (const float*)d_in[10];
    const float* LN2W = (const float*)d_in[11];
    const float* LN2B = (const float*)d_in[12];
    const float* W2   = (const float*)d_in[13];
    const float* B2   = (const float*)d_in[14];

    float* OUT = (float*)d_out;                       // [B,S,HID]
    float* CM  = OUT + (size_t)B_ * S_ * H_ * 64;     // [B,H,S,D]

    static int attr_set = 0;
    if (!attr_set) {
        cudaFuncSetAttribute(mhba_hmma_kernel,
                             cudaFuncAttributeMaxDynamicSharedMemorySize, SMEM_TOTAL);
        attr_set = 1;
    }

    mhba_hmma_kernel<<<GRID, TPB, SMEM_TOTAL>>>(
        Qin, Kin, Vin, MEM, Wq, Wk, Wv, FG,
        LN1W, LN1B, W1, LN2W, LN2B, W2, B2, OUT, CM);
}